// round 3
// baseline (speedup 1.0000x reference)
#include <cuda_runtime.h>

#define NPIX (2048*2048)
#define NB   256
#define NRC  12          // 4 regions * 3 channels
#define FINE 512         // fine bins: 2*idx + (cdf_bin != idx)
#define GRID1 152
#define THR1  512
#define SMEM1 (NRC*FINE*8 + NRC*NB*4)   // 49152 + 12288 = 61440 bytes

// ---------------- global scratch (plain stores only; no zeroing needed) --------------
static __device__ unsigned long long g_pfine[GRID1][NRC*FINE]; // per-block fine tables
static __device__ unsigned           g_ptar [GRID1][NRC*NB];   // per-block tar hists
static __device__ double             g_loss_rc[NRC];
static __device__ int                g_ctr;                    // zero-init; reset each launch

// 3-bit region codes (region+1; 0 = none) packed LSB-first per label 0..18.
// regions: 0=face, 1=hair, 2=eyeL, 3=eyeR
// src face labels {1,7,8,10,11,14}; tar face labels drop 11 (reference keeps mask_A==11
// separately via the "bug": mask_B_face += (mask_A == 11)).
#define CODEBASE ( (1ULL<<3) | (3ULL<<6) | (4ULL<<9) | (3ULL<<12) | (4ULL<<15) \
                 | (1ULL<<21) | (1ULL<<24) | (1ULL<<30) | (1ULL<<42) | (2ULL<<51) )
#define SRCMAP (CODEBASE | (1ULL<<33))   // label 11 -> face (src only)
#define TARMAP (CODEBASE)                // label 11 -> none (tar)

__device__ __forceinline__ float dn(float x) {
    // exactly: clip((x+1)*0.5, 0, 1) * 255  with add->mul order (no fma contraction)
    return __fmul_rn(__saturatef(__fmul_rn(__fadd_rn(x, 1.0f), 0.5f)), 255.0f);
}

__device__ __forceinline__ void px(int la, int lb,
    float f0, float f1, float f2, float r0, float r1, float r2,
    unsigned long long* s_fine, unsigned* s_tar)
{
    const float CST = (float)(256.0 / 255.0);
    int rs = (int)((SRCMAP >> (3*la)) & 7ULL) - 1;
    int rt = (int)((TARMAP >> (3*lb)) & 7ULL) - 1;
    int extra = (la == 11) ? 1 : 0;

    if (rs >= 0) {
        float vv[3] = {dn(f0), dn(f1), dn(f2)};
        unsigned long long* base = s_fine + rs*3*FINE;
        #pragma unroll
        for (int c = 0; c < 3; c++) {
            float v  = vv[c];
            int idx  = (int)v;                       // floor (v>=0)
            int cb   = (int)__fmul_rn(v, CST);       // floor(v*256/255)
            if (cb > 255) cb = 255;
            float fr = v - (float)idx;               // exact
            unsigned un = (unsigned)(fr * 1048576.0f + 0.5f);   // frac in 2^-20 units
            int f = 2*idx + ((cb > idx) ? 1 : 0);
            atomicAdd(base + c*FINE + f, (1ULL << 40) + (unsigned long long)un);
        }
    }
    int fm = ((rt == 0) ? 1 : 0) + extra;            // tar face mask value (can be 2)
    if (fm || rt > 0) {
        float vv[3] = {dn(r0), dn(r1), dn(r2)};
        if (fm) {
            float m = (float)fm;
            #pragma unroll
            for (int c = 0; c < 3; c++) {
                int bb = (int)__fmul_rn(__fmul_rn(vv[c], m), CST);
                if (bb > 255) bb = 255;
                atomicAdd(&s_tar[c*NB + bb], 1u);    // face rows = rc 0..2
            }
        }
        if (rt > 0) {
            unsigned* tb = s_tar + rt*3*NB;
            #pragma unroll
            for (int c = 0; c < 3; c++) {
                int bb = (int)__fmul_rn(vv[c], CST);
                if (bb > 255) bb = 255;
                atomicAdd(tb + c*NB + bb, 1u);
            }
        }
    }
}

// ---------------- pass 1: one streaming pass, shared packed histograms ---------------
__global__ void __launch_bounds__(THR1) hm_pass1(
    const float4* __restrict__ fa, const float4* __restrict__ rb,
    const int4* __restrict__ ma, const int4* __restrict__ mb)
{
    extern __shared__ unsigned char smem[];
    unsigned long long* s_fine = (unsigned long long*)smem;                // [NRC*FINE]
    unsigned* s_tar = (unsigned*)(smem + NRC*FINE*sizeof(unsigned long long)); // [NRC*NB]

    for (int i = threadIdx.x; i < NRC*FINE; i += THR1) s_fine[i] = 0ULL;
    for (int i = threadIdx.x; i < NRC*NB;  i += THR1) s_tar[i]  = 0u;
    __syncthreads();

    const int n4 = NPIX / 4;
    const int stride = gridDim.x * blockDim.x;
    for (int g = blockIdx.x * blockDim.x + threadIdx.x; g < n4; g += stride) {
        int4   a  = ma[g];
        int4   b  = mb[g];
        float4 f0 = fa[g];
        float4 f1 = fa[g +     n4];
        float4 f2 = fa[g + 2 * n4];
        float4 r0 = rb[g];
        float4 r1 = rb[g +     n4];
        float4 r2 = rb[g + 2 * n4];
        px(a.x, b.x, f0.x, f1.x, f2.x, r0.x, r1.x, r2.x, s_fine, s_tar);
        px(a.y, b.y, f0.y, f1.y, f2.y, r0.y, r1.y, r2.y, s_fine, s_tar);
        px(a.z, b.z, f0.z, f1.z, f2.z, r0.z, r1.z, r2.z, s_fine, s_tar);
        px(a.w, b.w, f0.w, f1.w, f2.w, r0.w, r1.w, r2.w, s_fine, s_tar);
    }
    __syncthreads();

    // plain coalesced flush (no global atomics)
    unsigned long long* pf = g_pfine[blockIdx.x];
    for (int i = threadIdx.x; i < NRC*FINE; i += THR1) pf[i] = s_fine[i];
    unsigned* pt = g_ptar[blockIdx.x];
    for (int i = threadIdx.x; i < NRC*NB; i += THR1) pt[i] = s_tar[i];
}

// ---------------- pass 2: reduce partials, CDFs, table, closed-form loss -------------
__global__ void __launch_bounds__(1024) hm_pass2(float* __restrict__ out)
{
    const int rc = blockIdx.x;      // region*3 + channel
    const int tid = threadIdx.x;

    __shared__ unsigned           s_fc[FINE];
    __shared__ unsigned long long s_fu[FINE];
    __shared__ unsigned           s_th[NB];
    __shared__ unsigned           s_hist[NB], s_cnt[NB], s_ri[NB];
    __shared__ unsigned long long s_un[NB];
    __shared__ float              s_sc[2*NB];
    __shared__ double             s_rd[NB];

    if (tid < FINE) { s_fc[tid] = 0u; s_fu[tid] = 0ULL; }
    if (tid < NB)   s_th[tid] = 0u;
    __syncthreads();

    // reduce fine partials: 2 halves of GRID1 blocks
    {
        int f = tid & (FINE-1), h = tid >> 9;
        unsigned c = 0; unsigned long long u = 0;
        int b0 = h * (GRID1/2);
        #pragma unroll 4
        for (int b = b0; b < b0 + GRID1/2; b++) {
            unsigned long long p = g_pfine[b][rc*FINE + f];
            c += (unsigned)(p >> 40);
            u += (p & ((1ULL << 40) - 1ULL));
        }
        atomicAdd(&s_fc[f], c);
        atomicAdd(&s_fu[f], u);
    }
    // reduce tar partials: 4 quarters
    {
        int i = tid & (NB-1), q = tid >> 8;
        unsigned c = 0;
        int b0 = q * (GRID1/4);
        #pragma unroll 4
        for (int b = b0; b < b0 + GRID1/4; b++) c += g_ptar[b][rc*NB + i];
        atomicAdd(&s_th[i], c);
    }
    __syncthreads();

    // per-idx stats and src cdf-histogram from fine bins
    if (tid < NB) {
        unsigned c0 = s_fc[2*tid], c1 = s_fc[2*tid+1];
        s_cnt[tid]  = c0 + c1;
        s_un[tid]   = s_fu[2*tid] + s_fu[2*tid+1];
        s_hist[tid] = c0 + (tid ? s_fc[2*tid-1] : 0u);  // bins with cdf_bin == tid
    }
    __syncthreads();

    // totals
    if (tid < NB) s_ri[tid] = s_hist[tid];
    __syncthreads();
    for (int off = NB/2; off; off >>= 1) { if (tid < off) s_ri[tid] += s_ri[tid+off]; __syncthreads(); }
    unsigned tot_s = s_ri[0];
    __syncthreads();
    if (tid < NB) s_ri[tid] = s_th[tid];
    __syncthreads();
    for (int off = NB/2; off; off >>= 1) { if (tid < off) s_ri[tid] += s_ri[tid+off]; __syncthreads(); }
    unsigned tot_t = s_ri[0];
    __syncthreads();

    // normalized f32 CDFs (Kogge-Stone scan, two halves in parallel)
    if (tid < 2*NB) {
        int i = tid & (NB-1), w = tid >> 8;
        float den = fmaxf((float)(w ? tot_t : tot_s), 1.0f);
        s_sc[tid] = (float)(w ? s_th[i] : s_hist[i]) / den;
    }
    __syncthreads();
    for (int off = 1; off < NB; off <<= 1) {
        float t = 0.0f;
        int i = tid & (NB-1);
        if (tid < 2*NB && i >= off) t = s_sc[tid - off];
        __syncthreads();
        if (tid < 2*NB && i >= off) s_sc[tid] += t;
        __syncthreads();
    }

    // transfer table + closed-form L1 contribution
    if (tid < NB) {
        int t;
        if (tid == 0)            t = 0;
        else if (tid == NB - 1)  t = NB - 1;
        else {
            float d = s_sc[tid];
            t = tid;
            for (int j = 1; j < NB; j++) {
                if (d >= s_sc[NB + j - 1] && d <= s_sc[NB + j]) { t = j; break; }
            }
        }
        // values v in [tid, tid+1): sign of (v - t) fixed by (t <= tid)
        double s  = (double)s_cnt[tid] * (double)tid
                  + (double)s_un[tid] * (1.0 / 1048576.0);
        double cT = (double)s_cnt[tid] * (double)t;
        s_rd[tid] = (t <= tid) ? (s - cT) : (cT - s);
    }
    __syncthreads();
    for (int off = NB/2; off; off >>= 1) { if (tid < off) s_rd[tid] += s_rd[tid+off]; __syncthreads(); }

    if (tid == 0) {
        g_loss_rc[rc] = s_rd[0];
        __threadfence();
        int old = atomicAdd(&g_ctr, 1);
        if (old == NRC - 1) {
            __threadfence();
            double tot = 0.0;
            #pragma unroll
            for (int r = 0; r < NRC; r++) tot += g_loss_rc[r];
            out[0] = (float)(0.1 * tot / (3.0 * (double)NPIX));
            g_ctr = 0;   // reset for next graph replay
        }
    }
}

extern "C" void kernel_launch(void* const* d_in, const int* in_sizes, int n_in,
                              void* d_out, int out_size)
{
    const float4* fa = (const float4*)d_in[0];
    const float4* rb = (const float4*)d_in[1];
    const int4*   ma = (const int4*)d_in[2];
    const int4*   mb = (const int4*)d_in[3];

    cudaFuncSetAttribute(hm_pass1, cudaFuncAttributeMaxDynamicSharedMemorySize, SMEM1);
    hm_pass1<<<GRID1, THR1, SMEM1>>>(fa, rb, ma, mb);
    hm_pass2<<<NRC, 1024>>>((float*)d_out);
}

// round 8
// speedup vs baseline: 1.2834x; 1.2834x over previous
#include <cuda_runtime.h>

#define NPIX (2048*2048)
#define NB   256
#define NRC  12          // 4 regions * 3 channels
#define FINE 512         // fine bins: 2*idx + (cdf_bin != idx)
#define GRID1 304        // 2 blocks/SM
#define THR1  512
#define SMEM1 (NRC*FINE*8 + NRC*NB*4)   // 49152 + 12288 = 61440 bytes

// ---------------- global accumulators (zero-init; pass2 re-zeros each launch) --------
static __device__ unsigned long long g_fine[NRC*FINE];
static __device__ unsigned           g_tar [NRC*NB];
static __device__ double             g_loss_rc[NRC];
static __device__ int                g_ctr;

// 3-bit region codes (region+1; 0 = none) packed LSB-first per label 0..18.
// regions: 0=face, 1=hair, 2=eyeL, 3=eyeR
// src face labels {1,7,8,10,11,14}; tar face labels drop 11 (the reference "bug" adds
// mask_A==11 to the tar face mask separately).
#define CODEBASE ( (1ULL<<3) | (3ULL<<6) | (4ULL<<9) | (3ULL<<12) | (4ULL<<15) \
                 | (1ULL<<21) | (1ULL<<24) | (1ULL<<30) | (1ULL<<42) | (2ULL<<51) )
#define SRCMAP (CODEBASE | (1ULL<<33))   // label 11 -> face (src only)
#define TARMAP (CODEBASE)                // label 11 -> none (tar)

__device__ __forceinline__ float dn(float x) {
    // exactly: clip((x+1)*0.5, 0, 1) * 255, add->mul order, no fma contraction
    return __fmul_rn(__saturatef(__fmul_rn(__fadd_rn(x, 1.0f), 0.5f)), 255.0f);
}

__device__ __forceinline__ void px(int la, int lb,
    float f0, float f1, float f2, float r0, float r1, float r2,
    unsigned long long* s_fine, unsigned* s_tar)
{
    const float CST = (float)(256.0 / 255.0);
    int rs = (int)((SRCMAP >> (3*la)) & 7ULL) - 1;
    int rt = (int)((TARMAP >> (3*lb)) & 7ULL) - 1;
    int extra = (la == 11) ? 1 : 0;

    // ---- src: 1 packed u64 atomic per channel (count<<40 | frac*2^20) ----
    if (rs >= 0) {
        float vv[3] = {dn(f0), dn(f1), dn(f2)};
        unsigned long long* base = s_fine + rs*3*FINE;
        #pragma unroll
        for (int c = 0; c < 3; c++) {
            float v  = vv[c];
            int idx  = (int)v;                       // floor (v>=0)
            int cb   = (int)__fmul_rn(v, CST);       // floor(v*256/255), bit-exact w/ ref
            if (cb > 255) cb = 255;
            unsigned un = (unsigned)((v - (float)idx) * 1048576.0f + 0.5f);
            int f = 2*idx + ((cb > idx) ? 1 : 0);
            atomicAdd(base + c*FINE + f, (1ULL << 40) + (unsigned long long)un);
        }
    }

    // ---- tar: unified primary (face-mask path OR region path), rare secondary ----
    int fm = ((rt == 0) ? 1 : 0) + extra;            // face mask value (0,1,2)
    if (fm | (rt > 0)) {
        float vv[3] = {dn(r0), dn(r1), dn(r2)};
        int base = fm ? 0 : rt*3*NB;                 // face table rows are rc 0..2
        float m  = (float)fm;
        #pragma unroll
        for (int c = 0; c < 3; c++) {
            float u = fm ? __fmul_rn(vv[c], m) : vv[c];
            int bb = (int)__fmul_rn(u, CST);
            if (bb > 255) bb = 255;
            atomicAdd(&s_tar[base + c*NB + bb], 1u);
        }
        // double-contribution: mask_A==11 (face extra) AND tar pixel in hair/eye
        if (extra & (rt > 0)) {
            #pragma unroll
            for (int c = 0; c < 3; c++) {
                int bb = (int)__fmul_rn(vv[c], CST);
                if (bb > 255) bb = 255;
                atomicAdd(&s_tar[rt*3*NB + c*NB + bb], 1u);
            }
        }
    }
}

// ---------------- pass 1: streaming pass, shared hist, global-atomic flush -----------
__global__ void __launch_bounds__(THR1, 2) hm_pass1(
    const float4* __restrict__ fa, const float4* __restrict__ rb,
    const int4* __restrict__ ma, const int4* __restrict__ mb)
{
    extern __shared__ unsigned char smem[];
    unsigned long long* s_fine = (unsigned long long*)smem;                     // [NRC*FINE]
    unsigned* s_tar = (unsigned*)(smem + NRC*FINE*sizeof(unsigned long long));  // [NRC*NB]

    for (int i = threadIdx.x; i < NRC*FINE; i += THR1) s_fine[i] = 0ULL;
    for (int i = threadIdx.x; i < NRC*NB;  i += THR1) s_tar[i]  = 0u;
    __syncthreads();

    const int n4 = NPIX / 4;
    const int stride = gridDim.x * blockDim.x;
    for (int g = blockIdx.x * blockDim.x + threadIdx.x; g < n4; g += stride) {
        int4   a  = ma[g];
        int4   b  = mb[g];
        float4 f0 = fa[g];
        float4 f1 = fa[g +     n4];
        float4 f2 = fa[g + 2 * n4];
        float4 r0 = rb[g];
        float4 r1 = rb[g +     n4];
        float4 r2 = rb[g + 2 * n4];
        px(a.x, b.x, f0.x, f1.x, f2.x, r0.x, r1.x, r2.x, s_fine, s_tar);
        px(a.y, b.y, f0.y, f1.y, f2.y, r0.y, r1.y, r2.y, s_fine, s_tar);
        px(a.z, b.z, f0.z, f1.z, f2.z, r0.z, r1.z, r2.z, s_fine, s_tar);
        px(a.w, b.w, f0.w, f1.w, f2.w, r0.w, r1.w, r2.w, s_fine, s_tar);
    }
    __syncthreads();

    // flush: global atomics into small tables (spread addresses -> L2-pipelined)
    for (int i = threadIdx.x; i < NRC*FINE; i += THR1) {
        unsigned long long v = s_fine[i];
        if (v) atomicAdd(&g_fine[i], v);
    }
    for (int i = threadIdx.x; i < NRC*NB; i += THR1) {
        unsigned v = s_tar[i];
        if (v) atomicAdd(&g_tar[i], v);
    }
}

// ---------------- pass 2: CDFs, transfer table, closed-form loss (tiny) --------------
__global__ void __launch_bounds__(1024) hm_pass2(float* __restrict__ out)
{
    const int rc = blockIdx.x;      // region*3 + channel
    const int tid = threadIdx.x;

    __shared__ unsigned           s_fc[FINE];
    __shared__ unsigned long long s_fu[FINE];
    __shared__ unsigned           s_th[NB];
    __shared__ unsigned           s_hist[NB], s_cnt[NB], s_ri[NB];
    __shared__ unsigned long long s_un[NB];
    __shared__ float              s_sc[2*NB];
    __shared__ double             s_rd[NB];

    if (tid < FINE) {
        unsigned long long p = g_fine[rc*FINE + tid];
        g_fine[rc*FINE + tid] = 0ULL;               // reset for next graph replay
        s_fc[tid] = (unsigned)(p >> 40);
        s_fu[tid] = p & ((1ULL << 40) - 1ULL);
    }
    if (tid < NB) {
        s_th[tid] = g_tar[rc*NB + tid];
        g_tar[rc*NB + tid] = 0u;                    // reset for next graph replay
    }
    __syncthreads();

    // per-idx stats + src cdf-histogram from fine bins
    if (tid < NB) {
        unsigned c0 = s_fc[2*tid], c1 = s_fc[2*tid+1];
        s_cnt[tid]  = c0 + c1;
        s_un[tid]   = s_fu[2*tid] + s_fu[2*tid+1];
        s_hist[tid] = c0 + (tid ? s_fc[2*tid-1] : 0u);  // bins with cdf_bin == tid
    }
    __syncthreads();

    // totals
    if (tid < NB) s_ri[tid] = s_hist[tid];
    __syncthreads();
    for (int off = NB/2; off; off >>= 1) { if (tid < off) s_ri[tid] += s_ri[tid+off]; __syncthreads(); }
    unsigned tot_s = s_ri[0];
    __syncthreads();
    if (tid < NB) s_ri[tid] = s_th[tid];
    __syncthreads();
    for (int off = NB/2; off; off >>= 1) { if (tid < off) s_ri[tid] += s_ri[tid+off]; __syncthreads(); }
    unsigned tot_t = s_ri[0];
    __syncthreads();

    // normalized f32 CDFs (Kogge-Stone, src and tar scanned in parallel halves)
    if (tid < 2*NB) {
        int i = tid & (NB-1), w = tid >> 8;
        float den = fmaxf((float)(w ? tot_t : tot_s), 1.0f);
        s_sc[tid] = (float)(w ? s_th[i] : s_hist[i]) / den;
    }
    __syncthreads();
    for (int off = 1; off < NB; off <<= 1) {
        float t = 0.0f;
        int i = tid & (NB-1);
        if (tid < 2*NB && i >= off) t = s_sc[tid - off];
        __syncthreads();
        if (tid < 2*NB && i >= off) s_sc[tid] += t;
        __syncthreads();
    }

    // transfer table + closed-form L1 contribution
    if (tid < NB) {
        int t;
        if (tid == 0)            t = 0;
        else if (tid == NB - 1)  t = NB - 1;
        else {
            float d = s_sc[tid];
            t = tid;
            for (int j = 1; j < NB; j++) {
                if (d >= s_sc[NB + j - 1] && d <= s_sc[NB + j]) { t = j; break; }
            }
        }
        // values v in [tid, tid+1): sign of (v - t) fixed by (t <= tid)
        double s  = (double)s_cnt[tid] * (double)tid
                  + (double)s_un[tid] * (1.0 / 1048576.0);
        double cT = (double)s_cnt[tid] * (double)t;
        s_rd[tid] = (t <= tid) ? (s - cT) : (cT - s);
    }
    __syncthreads();
    for (int off = NB/2; off; off >>= 1) { if (tid < off) s_rd[tid] += s_rd[tid+off]; __syncthreads(); }

    if (tid == 0) {
        g_loss_rc[rc] = s_rd[0];
        __threadfence();
        int old = atomicAdd(&g_ctr, 1);
        if (old == NRC - 1) {
            __threadfence();
            double tot = 0.0;
            #pragma unroll
            for (int r = 0; r < NRC; r++) tot += g_loss_rc[r];
            out[0] = (float)(0.1 * tot / (3.0 * (double)NPIX));
            g_ctr = 0;   // reset for next graph replay
        }
    }
}

extern "C" void kernel_launch(void* const* d_in, const int* in_sizes, int n_in,
                              void* d_out, int out_size)
{
    const float4* fa = (const float4*)d_in[0];
    const float4* rb = (const float4*)d_in[1];
    const int4*   ma = (const int4*)d_in[2];
    const int4*   mb = (const int4*)d_in[3];

    cudaFuncSetAttribute(hm_pass1, cudaFuncAttributeMaxDynamicSharedMemorySize, SMEM1);
    hm_pass1<<<GRID1, THR1, SMEM1>>>(fa, rb, ma, mb);
    hm_pass2<<<NRC, 1024>>>((float*)d_out);
}